// round 1
// baseline (speedup 1.0000x reference)
#include <cuda_runtime.h>
#include <cstdint>

#define BATCH 4
#define DDIM 256
#define NSEQ 4096
#define KCB 8192
#define MTOT (BATCH * NSEQ)      // 16384 queries
#define NSPLIT 8
#define KSEG (KCB / NSPLIT)      // 1024 codes per split
#define TM 128
#define TKT 128
#define TD 16

// Static scratch (no allocations allowed in kernel_launch)
__device__ float g_eT[(size_t)DDIM * KCB];      // e transposed [D, K], 8.4 MB
__device__ float g_e2[KCB];                     // ||e_k||^2
__device__ float g_pmin[NSPLIT * MTOT];         // per-split partial min
__device__ int   g_pidx[NSPLIT * MTOT];         // per-split partial argmin
__device__ int   g_codes[MTOT];                 // final codes

// ---------------------------------------------------------------------------
// Transpose e [K, D] -> g_eT [D, K] (coalesced both sides via 32x32 smem tile)
// ---------------------------------------------------------------------------
__global__ void transpose_e_kernel(const float* __restrict__ e) {
    __shared__ float s[32][33];
    const int k0 = blockIdx.x * 32;
    const int d0 = blockIdx.y * 32;
    const int tx = threadIdx.x;  // 32
    const int ty = threadIdx.y;  // 8
#pragma unroll
    for (int j = 0; j < 4; j++) {
        int r = ty + j * 8;
        s[r][tx] = e[(size_t)(k0 + r) * DDIM + d0 + tx];
    }
    __syncthreads();
#pragma unroll
    for (int j = 0; j < 4; j++) {
        int r = ty + j * 8;
        g_eT[(size_t)(d0 + r) * KCB + k0 + tx] = s[tx][r];
    }
}

// ---------------------------------------------------------------------------
// e2[k] = sum_d e[k,d]^2 (one warp per codeword, fp64 accumulation)
// ---------------------------------------------------------------------------
__global__ void e2_kernel(const float* __restrict__ e) {
    const int w = (blockIdx.x * blockDim.x + threadIdx.x) >> 5;
    const int lane = threadIdx.x & 31;
    double acc = 0.0;
#pragma unroll
    for (int j = 0; j < 8; j++) {
        float v = e[(size_t)w * DDIM + lane + 32 * j];
        acc += (double)v * (double)v;
    }
#pragma unroll
    for (int off = 16; off; off >>= 1)
        acc += __shfl_down_sync(0xffffffffu, acc, off);
    if (lane == 0) g_e2[w] = (float)acc;
}

// ---------------------------------------------------------------------------
// Main: tiled SGEMM (scores = e2 - 2*x.e) with fused running argmin.
// Grid: (MTOT/TM, NSPLIT). Block: 256 threads = 16x16, 8x8 frags each.
// ---------------------------------------------------------------------------
__global__ __launch_bounds__(256, 2) void vq_main_kernel(const float* __restrict__ x) {
    __shared__ float xs[TD][TM];
    __shared__ float es[TD][TKT];
    __shared__ float e2s[TKT];

    const int t  = threadIdx.x;
    const int tx = t & 15;   // code-tile direction
    const int ty = t >> 4;   // query direction
    const int q0 = blockIdx.x * TM;            // tiles never straddle b (N%TM==0)
    const int b  = q0 / NSEQ;
    const int n0 = q0 % NSEQ;
    const int seg0 = blockIdx.y * KSEG;
    const float* xbase = x + (size_t)b * DDIM * NSEQ + n0;

    float bestv[8];
    int   besti[8];
#pragma unroll
    for (int i = 0; i < 8; i++) { bestv[i] = 3.402823466e38f; besti[i] = 0x7fffffff; }

    for (int kt = 0; kt < KSEG / TKT; ++kt) {
        const int k0 = seg0 + kt * TKT;
        float acc[8][8];
#pragma unroll
        for (int i = 0; i < 8; i++)
#pragma unroll
            for (int j = 0; j < 8; j++) acc[i][j] = 0.0f;

        for (int ds = 0; ds < DDIM / TD; ++ds) {
            const int d0 = ds * TD;
            __syncthreads();
            // Stage TD x TM of x and TD x TKT of eT. 2 float4 each per thread.
#pragma unroll
            for (int r = 0; r < 2; ++r) {
                int f  = t + r * 256;
                int dd = f >> 5;
                int c4 = (f & 31) << 2;
                float4 xv = *reinterpret_cast<const float4*>(
                    xbase + (size_t)(d0 + dd) * NSEQ + c4);
                *reinterpret_cast<float4*>(&xs[dd][c4]) = xv;
                float4 ev = *reinterpret_cast<const float4*>(
                    &g_eT[(size_t)(d0 + dd) * KCB + k0 + c4]);
                *reinterpret_cast<float4*>(&es[dd][c4]) = ev;
            }
            __syncthreads();
#pragma unroll
            for (int dd = 0; dd < TD; ++dd) {
                float a[8], bb[8];
                *reinterpret_cast<float4*>(&a[0])  = *reinterpret_cast<const float4*>(&xs[dd][ty * 8]);
                *reinterpret_cast<float4*>(&a[4])  = *reinterpret_cast<const float4*>(&xs[dd][ty * 8 + 4]);
                *reinterpret_cast<float4*>(&bb[0]) = *reinterpret_cast<const float4*>(&es[dd][tx * 8]);
                *reinterpret_cast<float4*>(&bb[4]) = *reinterpret_cast<const float4*>(&es[dd][tx * 8 + 4]);
#pragma unroll
                for (int i = 0; i < 8; i++)
#pragma unroll
                    for (int j = 0; j < 8; j++)
                        acc[i][j] = fmaf(a[i], bb[j], acc[i][j]);
            }
        }
        // Epilogue: score = e2[k] - 2*dot; update running argmin (first-index ties)
        __syncthreads();
        if (t < TKT) e2s[t] = g_e2[k0 + t];
        __syncthreads();
#pragma unroll
        for (int i = 0; i < 8; i++) {
#pragma unroll
            for (int j = 0; j < 8; j++) {
                int kk = tx * 8 + j;
                float sc = fmaf(-2.0f, acc[i][j], e2s[kk]);
                int kg = k0 + kk;
                if (sc < bestv[i] || (sc == bestv[i] && kg < besti[i])) {
                    bestv[i] = sc; besti[i] = kg;
                }
            }
        }
    }

    // Reduce across the 16 tx-lanes sharing each query row (half-warp shuffle;
    // contaminated intermediates in lanes >=8 are never consumed by lane 0/16).
#pragma unroll
    for (int i = 0; i < 8; i++) {
        float v = bestv[i]; int ix = besti[i];
#pragma unroll
        for (int off = 8; off; off >>= 1) {
            float ov = __shfl_down_sync(0xffffffffu, v, off);
            int   oi = __shfl_down_sync(0xffffffffu, ix, off);
            if (ov < v || (ov == v && oi < ix)) { v = ov; ix = oi; }
        }
        if (tx == 0) {
            int q = q0 + ty * 8 + i;
            g_pmin[blockIdx.y * MTOT + q] = v;
            g_pidx[blockIdx.y * MTOT + q] = ix;
        }
    }
}

// ---------------------------------------------------------------------------
// Reduce NSPLIT partials -> codes (lexicographic: min value, then min index)
// ---------------------------------------------------------------------------
__global__ void reduce_kernel() {
    const int q = blockIdx.x * blockDim.x + threadIdx.x;
    float bv = g_pmin[q];
    int   bi = g_pidx[q];
#pragma unroll
    for (int s = 1; s < NSPLIT; s++) {
        float v = g_pmin[s * MTOT + q];
        int  ix = g_pidx[s * MTOT + q];
        if (v < bv || (v == bv && ix < bi)) { bv = v; bi = ix; }
    }
    g_codes[q] = bi;
}

// ---------------------------------------------------------------------------
// Gather: out[b, d, n] = e[codes[b*N+n], d]. smem transpose for coalescing.
// Block handles 32 consecutive queries; d processed in chunks of 64.
// ---------------------------------------------------------------------------
__global__ void gather_kernel(const float* __restrict__ e, float* __restrict__ out) {
    __shared__ int   scode[32];
    __shared__ float tile[32][65];
    const int t  = threadIdx.x;
    const int q0 = blockIdx.x * 32;
    const int b  = q0 / NSEQ;
    const int n0 = q0 % NSEQ;
    if (t < 32) scode[t] = g_codes[q0 + t];
    __syncthreads();

    const int cl = t >> 3;          // 0..31: query within tile (load phase)
    const int dp = (t & 7) * 8;     // 0..56: d offset within chunk (load phase)
    const int c2 = t & 31;          // query (store phase)
    const int dg = t >> 5;          // 0..7  (store phase)
    const int code = scode[cl];

    for (int ch = 0; ch < 4; ch++) {
        const int d0 = ch * 64;
        float4 v0 = *reinterpret_cast<const float4*>(&e[(size_t)code * DDIM + d0 + dp]);
        float4 v1 = *reinterpret_cast<const float4*>(&e[(size_t)code * DDIM + d0 + dp + 4]);
        tile[cl][dp + 0] = v0.x; tile[cl][dp + 1] = v0.y;
        tile[cl][dp + 2] = v0.z; tile[cl][dp + 3] = v0.w;
        tile[cl][dp + 4] = v1.x; tile[cl][dp + 5] = v1.y;
        tile[cl][dp + 6] = v1.z; tile[cl][dp + 7] = v1.w;
        __syncthreads();
#pragma unroll
        for (int dd = 0; dd < 8; dd++) {
            int d = dd * 8 + dg;
            out[((size_t)b * DDIM + d0 + d) * NSEQ + n0 + c2] = tile[c2][d];
        }
        __syncthreads();
    }
}

// ---------------------------------------------------------------------------
extern "C" void kernel_launch(void* const* d_in, const int* in_sizes, int n_in,
                              void* d_out, int out_size) {
    const float* x = (const float*)d_in[0];  // [B, D, N] fp32
    const float* e = (const float*)d_in[1];  // [K, D]    fp32
    float* out = (float*)d_out;              // [B, D, N] fp32

    transpose_e_kernel<<<dim3(KCB / 32, DDIM / 32), dim3(32, 8)>>>(e);
    e2_kernel<<<(KCB * 32) / 256, 256>>>(e);
    vq_main_kernel<<<dim3(MTOT / TM, NSPLIT), 256>>>(x);
    reduce_kernel<<<MTOT / 256, 256>>>();
    gather_kernel<<<MTOT / 32, 256>>>(e, out);
}

// round 2
// speedup vs baseline: 1.0011x; 1.0011x over previous
#include <cuda_runtime.h>
#include <cstdint>

#define BATCH 4
#define DDIM 256
#define NSEQ 4096
#define KCB 8192
#define MTOT (BATCH * NSEQ)      // 16384 queries
#define NSPLIT 8
#define KSEG (KCB / NSPLIT)      // 1024 codes per split
#define TM 128
#define TKT 128
#define TD 16

// Static scratch (no allocations allowed in kernel_launch)
__device__ float g_eT[(size_t)DDIM * KCB];      // e transposed [D, K], 8.4 MB
__device__ float g_e2[KCB];                     // ||e_k||^2
__device__ float g_pmin[NSPLIT * MTOT];         // per-split partial min
__device__ int   g_pidx[NSPLIT * MTOT];         // per-split partial argmin
__device__ int   g_codes[MTOT];                 // final codes

// ---------------------------------------------------------------------------
// Transpose e [K, D] -> g_eT [D, K] (coalesced both sides via 32x32 smem tile)
// ---------------------------------------------------------------------------
__global__ void transpose_e_kernel(const float* __restrict__ e) {
    __shared__ float s[32][33];
    const int k0 = blockIdx.x * 32;
    const int d0 = blockIdx.y * 32;
    const int tx = threadIdx.x;  // 32
    const int ty = threadIdx.y;  // 8
#pragma unroll
    for (int j = 0; j < 4; j++) {
        int r = ty + j * 8;
        s[r][tx] = e[(size_t)(k0 + r) * DDIM + d0 + tx];
    }
    __syncthreads();
#pragma unroll
    for (int j = 0; j < 4; j++) {
        int r = ty + j * 8;
        g_eT[(size_t)(d0 + r) * KCB + k0 + tx] = s[tx][r];
    }
}

// ---------------------------------------------------------------------------
// e2[k] = sum_d e[k,d]^2 (one warp per codeword, fp64 accumulation)
// ---------------------------------------------------------------------------
__global__ void e2_kernel(const float* __restrict__ e) {
    const int w = (blockIdx.x * blockDim.x + threadIdx.x) >> 5;
    const int lane = threadIdx.x & 31;
    double acc = 0.0;
#pragma unroll
    for (int j = 0; j < 8; j++) {
        float v = e[(size_t)w * DDIM + lane + 32 * j];
        acc += (double)v * (double)v;
    }
#pragma unroll
    for (int off = 16; off; off >>= 1)
        acc += __shfl_down_sync(0xffffffffu, acc, off);
    if (lane == 0) g_e2[w] = (float)acc;
}

// ---------------------------------------------------------------------------
// Main: tiled SGEMM (scores = e2 - 2*x.e) with fused running argmin.
// Grid: (MTOT/TM, NSPLIT). Block: 256 threads = 16x16, 8x8 frags each.
// ---------------------------------------------------------------------------
__global__ __launch_bounds__(256, 2) void vq_main_kernel(const float* __restrict__ x) {
    __shared__ float xs[TD][TM];
    __shared__ float es[TD][TKT];
    __shared__ float e2s[TKT];

    const int t  = threadIdx.x;
    const int tx = t & 15;   // code-tile direction
    const int ty = t >> 4;   // query direction
    const int q0 = blockIdx.x * TM;            // tiles never straddle b (N%TM==0)
    const int b  = q0 / NSEQ;
    const int n0 = q0 % NSEQ;
    const int seg0 = blockIdx.y * KSEG;
    const float* xbase = x + (size_t)b * DDIM * NSEQ + n0;

    float bestv[8];
    int   besti[8];
#pragma unroll
    for (int i = 0; i < 8; i++) { bestv[i] = 3.402823466e38f; besti[i] = 0x7fffffff; }

    for (int kt = 0; kt < KSEG / TKT; ++kt) {
        const int k0 = seg0 + kt * TKT;
        float acc[8][8];
#pragma unroll
        for (int i = 0; i < 8; i++)
#pragma unroll
            for (int j = 0; j < 8; j++) acc[i][j] = 0.0f;

        for (int ds = 0; ds < DDIM / TD; ++ds) {
            const int d0 = ds * TD;
            __syncthreads();
            // Stage TD x TM of x and TD x TKT of eT. 2 float4 each per thread.
#pragma unroll
            for (int r = 0; r < 2; ++r) {
                int f  = t + r * 256;
                int dd = f >> 5;
                int c4 = (f & 31) << 2;
                float4 xv = *reinterpret_cast<const float4*>(
                    xbase + (size_t)(d0 + dd) * NSEQ + c4);
                *reinterpret_cast<float4*>(&xs[dd][c4]) = xv;
                float4 ev = *reinterpret_cast<const float4*>(
                    &g_eT[(size_t)(d0 + dd) * KCB + k0 + c4]);
                *reinterpret_cast<float4*>(&es[dd][c4]) = ev;
            }
            __syncthreads();
#pragma unroll
            for (int dd = 0; dd < TD; ++dd) {
                float a[8], bb[8];
                *reinterpret_cast<float4*>(&a[0])  = *reinterpret_cast<const float4*>(&xs[dd][ty * 8]);
                *reinterpret_cast<float4*>(&a[4])  = *reinterpret_cast<const float4*>(&xs[dd][ty * 8 + 4]);
                *reinterpret_cast<float4*>(&bb[0]) = *reinterpret_cast<const float4*>(&es[dd][tx * 8]);
                *reinterpret_cast<float4*>(&bb[4]) = *reinterpret_cast<const float4*>(&es[dd][tx * 8 + 4]);
#pragma unroll
                for (int i = 0; i < 8; i++)
#pragma unroll
                    for (int j = 0; j < 8; j++)
                        acc[i][j] = fmaf(a[i], bb[j], acc[i][j]);
            }
        }
        // Epilogue: score = e2[k] - 2*dot; update running argmin (first-index ties)
        __syncthreads();
        if (t < TKT) e2s[t] = g_e2[k0 + t];
        __syncthreads();
#pragma unroll
        for (int i = 0; i < 8; i++) {
#pragma unroll
            for (int j = 0; j < 8; j++) {
                int kk = tx * 8 + j;
                float sc = fmaf(-2.0f, acc[i][j], e2s[kk]);
                int kg = k0 + kk;
                if (sc < bestv[i] || (sc == bestv[i] && kg < besti[i])) {
                    bestv[i] = sc; besti[i] = kg;
                }
            }
        }
    }

    // Reduce across the 16 tx-lanes sharing each query row (half-warp shuffle;
    // contaminated intermediates in lanes >=8 are never consumed by lane 0/16).
#pragma unroll
    for (int i = 0; i < 8; i++) {
        float v = bestv[i]; int ix = besti[i];
#pragma unroll
        for (int off = 8; off; off >>= 1) {
            float ov = __shfl_down_sync(0xffffffffu, v, off);
            int   oi = __shfl_down_sync(0xffffffffu, ix, off);
            if (ov < v || (ov == v && oi < ix)) { v = ov; ix = oi; }
        }
        if (tx == 0) {
            int q = q0 + ty * 8 + i;
            g_pmin[blockIdx.y * MTOT + q] = v;
            g_pidx[blockIdx.y * MTOT + q] = ix;
        }
    }
}

// ---------------------------------------------------------------------------
// Reduce NSPLIT partials -> codes (lexicographic: min value, then min index)
// ---------------------------------------------------------------------------
__global__ void reduce_kernel() {
    const int q = blockIdx.x * blockDim.x + threadIdx.x;
    float bv = g_pmin[q];
    int   bi = g_pidx[q];
#pragma unroll
    for (int s = 1; s < NSPLIT; s++) {
        float v = g_pmin[s * MTOT + q];
        int  ix = g_pidx[s * MTOT + q];
        if (v < bv || (v == bv && ix < bi)) { bv = v; bi = ix; }
    }
    g_codes[q] = bi;
}

// ---------------------------------------------------------------------------
// Gather: out[b, d, n] = e[codes[b*N+n], d]. smem transpose for coalescing.
// Block handles 32 consecutive queries; d processed in chunks of 64.
// ---------------------------------------------------------------------------
__global__ void gather_kernel(const float* __restrict__ e, float* __restrict__ out) {
    __shared__ int   scode[32];
    __shared__ float tile[32][65];
    const int t  = threadIdx.x;
    const int q0 = blockIdx.x * 32;
    const int b  = q0 / NSEQ;
    const int n0 = q0 % NSEQ;
    if (t < 32) scode[t] = g_codes[q0 + t];
    __syncthreads();

    const int cl = t >> 3;          // 0..31: query within tile (load phase)
    const int dp = (t & 7) * 8;     // 0..56: d offset within chunk (load phase)
    const int c2 = t & 31;          // query (store phase)
    const int dg = t >> 5;          // 0..7  (store phase)
    const int code = scode[cl];

    for (int ch = 0; ch < 4; ch++) {
        const int d0 = ch * 64;
        float4 v0 = *reinterpret_cast<const float4*>(&e[(size_t)code * DDIM + d0 + dp]);
        float4 v1 = *reinterpret_cast<const float4*>(&e[(size_t)code * DDIM + d0 + dp + 4]);
        tile[cl][dp + 0] = v0.x; tile[cl][dp + 1] = v0.y;
        tile[cl][dp + 2] = v0.z; tile[cl][dp + 3] = v0.w;
        tile[cl][dp + 4] = v1.x; tile[cl][dp + 5] = v1.y;
        tile[cl][dp + 6] = v1.z; tile[cl][dp + 7] = v1.w;
        __syncthreads();
#pragma unroll
        for (int dd = 0; dd < 8; dd++) {
            int d = dd * 8 + dg;
            out[((size_t)b * DDIM + d0 + d) * NSEQ + n0 + c2] = tile[c2][d];
        }
        __syncthreads();
    }
}

// ---------------------------------------------------------------------------
extern "C" void kernel_launch(void* const* d_in, const int* in_sizes, int n_in,
                              void* d_out, int out_size) {
    const float* x = (const float*)d_in[0];  // [B, D, N] fp32
    const float* e = (const float*)d_in[1];  // [K, D]    fp32
    float* out = (float*)d_out;              // [B, D, N] fp32

    transpose_e_kernel<<<dim3(KCB / 32, DDIM / 32), dim3(32, 8)>>>(e);
    e2_kernel<<<(KCB * 32) / 256, 256>>>(e);
    vq_main_kernel<<<dim3(MTOT / TM, NSPLIT), 256>>>(x);
    reduce_kernel<<<MTOT / 256, 256>>>();
    gather_kernel<<<MTOT / 32, 256>>>(e, out);
}